// round 10
// baseline (speedup 1.0000x reference)
#include <cuda_runtime.h>
#include <cstdint>

// Problem constants (B=1)
#define DIM_D 32
#define DIM_H 64
#define DIM_W 128
#define DIM_C 96
#define S_WIN 64          // tokens per window (4*4*4)
#define NHEAD 4
#define CHEAD 24
#define NWIN  4096        // 8*16*32 windows
#define QS    100         // padded row stride for Q/K/V/X/O in smem (floats)
#define SCALE 0.20412414523193154f  // 24^-0.5

// smem layout (floats)
#define OFF_Q   0
#define OFF_K   6400
#define OFF_V   12800
#define OFF_X   19200     // X during QKV; reused as O after attention
#define OFF_W0  25600     // 96x96 weight staging buffer 0
#define OFF_W1  34816     // 96x96 weight staging buffer 1
#define SMEM_FLOATS 44032
#define SMEM_BYTES  (SMEM_FLOATS * 4)

typedef unsigned long long u64;

__device__ __forceinline__ u64 pack2(float lo, float hi) {
    u64 r;
    asm("mov.b64 %0, {%1, %2};" : "=l"(r) : "f"(lo), "f"(hi));
    return r;
}
__device__ __forceinline__ void fma2(u64& d, u64 a, u64 b) {
    asm("fma.rn.f32x2 %0, %1, %2, %0;" : "+l"(d) : "l"(a), "l"(b));
}
__device__ __forceinline__ u64 mul2(u64 a, u64 b) {
    u64 r;
    asm("mul.rn.f32x2 %0, %1, %2;" : "=l"(r) : "l"(a), "l"(b));
    return r;
}
__device__ __forceinline__ float red2(u64 v) {
    float lo, hi;
    asm("mov.b64 {%0, %1}, %2;" : "=f"(lo), "=f"(hi) : "l"(v));
    return lo + hi;
}

__device__ __forceinline__ void cp_async16(float* smem_dst, const float* gsrc) {
    uint32_t s = (uint32_t)__cvta_generic_to_shared(smem_dst);
    asm volatile("cp.async.ca.shared.global [%0], [%1], 16;" :: "r"(s), "l"(gsrc));
}
__device__ __forceinline__ void cp_commit() {
    asm volatile("cp.async.commit_group;");
}
template <int N>
__device__ __forceinline__ void cp_wait() {
    asm volatile("cp.async.wait_group %0;" :: "n"(N));
}

// stage a 96x96 float tile (row-major, row stride src_stride floats) into smem buf
__device__ __forceinline__ void stage_weights(float* buf, const float* gsrc,
                                              int src_stride, int tid) {
    #pragma unroll
    for (int i = 0; i < 9; i++) {
        int idx = tid + i * 256;       // < 2304 = 96*24
        int row = idx / 24;
        int c4  = idx % 24;
        cp_async16(buf + row * 96 + c4 * 4, gsrc + row * src_stride + c4 * 4);
    }
    cp_commit();
}

// GEMM: dst[r][n] = sum_c src[r][c] * W[c][n]   (src stride QS, 64 rows, 96 cols)
// warp owns rows r0..r0+7, lane owns cols {lane, lane+32, lane+64}; packed f32x2 over c.
__device__ __forceinline__ void gemm_96(const float* __restrict__ src,
                                        const float* __restrict__ W,
                                        float* __restrict__ dst,
                                        int r0, int lane) {
    u64 A0[8], A1[8], A2[8];
    #pragma unroll
    for (int i = 0; i < 8; i++) { A0[i] = 0ull; A1[i] = 0ull; A2[i] = 0ull; }

    #pragma unroll 8
    for (int c = 0; c < 96; c += 2) {
        u64 b0 = pack2(W[c * 96 + lane],      W[(c + 1) * 96 + lane]);
        u64 b1 = pack2(W[c * 96 + lane + 32], W[(c + 1) * 96 + lane + 32]);
        u64 b2 = pack2(W[c * 96 + lane + 64], W[(c + 1) * 96 + lane + 64]);
        #pragma unroll
        for (int i = 0; i < 8; i++) {
            u64 xv = *reinterpret_cast<const u64*>(src + (r0 + i) * QS + c); // broadcast
            fma2(A0[i], xv, b0);
            fma2(A1[i], xv, b1);
            fma2(A2[i], xv, b2);
        }
    }
    #pragma unroll
    for (int i = 0; i < 8; i++) {
        dst[(r0 + i) * QS + lane]      = red2(A0[i]);
        dst[(r0 + i) * QS + lane + 32] = red2(A1[i]);
        dst[(r0 + i) * QS + lane + 64] = red2(A2[i]);
    }
}

__global__ void __launch_bounds__(256, 1)
win3dattn_kernel(const float* __restrict__ x,
                 const float* __restrict__ w_qkv,
                 const float* __restrict__ w_proj,
                 const float* __restrict__ b_proj,
                 float* __restrict__ out)
{
    extern __shared__ float sm[];
    float* Qs = sm + OFF_Q;
    float* Ks = sm + OFF_K;
    float* Vs = sm + OFF_V;
    float* Xs = sm + OFF_X;    // X, later reused as O
    float* W0 = sm + OFF_W0;
    float* W1 = sm + OFF_W1;

    const int tid  = threadIdx.x;
    const int win  = blockIdx.x;
    const int wl   = win & 31;
    const int wm   = (win >> 5) & 15;
    const int wn   = win >> 9;
    const int d0 = wn * 4, h0 = wm * 4, w0 = wl * 4;

    // global float offset of token t's channel 0
    auto goff = [&](int t) -> int {
        int dd = d0 + (t >> 4);
        int hh = h0 + ((t >> 2) & 3);
        int ww = w0 + (t & 3);
        return ((dd * DIM_H + hh) * DIM_W + ww) * DIM_C;
    };

    // ---- stage w_qkv chunk0 (async), then load X, then stage chunk1 (async) ----
    stage_weights(W0, w_qkv + 0 * 96, 288, tid);               // group A

    #pragma unroll
    for (int i = 0; i < 6; i++) {
        int idx = tid + i * 256;           // < 1536 = 64*24
        int t  = idx / 24;
        int c4 = idx % 24;
        float4 v = *reinterpret_cast<const float4*>(x + goff(t) + c4 * 4);
        *reinterpret_cast<float4*>(Xs + t * QS + c4 * 4) = v;   // (t*QS*4B)%16==0
    }

    stage_weights(W1, w_qkv + 1 * 96, 288, tid);               // group B

    const int warp = tid >> 5;
    const int lane = tid & 31;
    const int r0   = warp * 8;

    cp_wait<1>();          // chunk0 landed (chunk1 may be in flight)
    __syncthreads();       // chunk0 + X visible to all

    // ---- Q = X @ Wq (buf0) ----
    gemm_96(Xs, W0, Qs, r0, lane);
    __syncthreads();       // all reads of W0 done

    stage_weights(W0, w_qkv + 2 * 96, 288, tid);               // group C (chunk2)
    cp_wait<1>();          // chunk1 landed
    __syncthreads();

    // ---- K = X @ Wk (buf1) ----
    gemm_96(Xs, W1, Ks, r0, lane);
    __syncthreads();       // all reads of W1 done

    stage_weights(W1, w_proj, 96, tid);                        // group D (w_proj)
    cp_wait<1>();          // chunk2 landed
    __syncthreads();

    // ---- V = X @ Wv (buf0) ----
    gemm_96(Xs, W0, Vs, r0, lane);

    // hoist bias loads: retire L2/DRAM latency under the attention phase
    float bb0 = b_proj[lane];
    float bb1 = b_proj[lane + 32];
    float bb2 = b_proj[lane + 64];

    __syncthreads();       // X fully consumed; safe to overwrite as O

    // ---- attention: one thread per (head, row), packed f32x2 ----
    {
        const int hd = tid >> 6;       // 0..3
        const int r  = tid & 63;       // 0..63
        const int co = hd * CHEAD;

        // Q row: 24 floats = 12 packed pairs ((r*QS + co) even -> 8B aligned)
        u64 qv[12];
        #pragma unroll
        for (int t = 0; t < 12; t++)
            qv[t] = *reinterpret_cast<const u64*>(Qs + r * QS + co + t * 2);

        float s[64];
        // 2 rows per iteration x 2 chains each = 4 independent FMA chains.
        // K rows are warp-uniform (broadcast) and 16B-aligned -> LDS.128.
        #pragma unroll
        for (int j = 0; j < 64; j += 2) {
            const ulonglong2* kA = reinterpret_cast<const ulonglong2*>(Ks + j * QS + co);
            const ulonglong2* kB = reinterpret_cast<const ulonglong2*>(Ks + (j + 1) * QS + co);
            ulonglong2 a_0 = kA[0], a_1 = kA[1], a_2 = kA[2];
            ulonglong2 a_3 = kA[3], a_4 = kA[4], a_5 = kA[5];
            ulonglong2 b_0 = kB[0], b_1 = kB[1], b_2 = kB[2];
            ulonglong2 b_3 = kB[3], b_4 = kB[4], b_5 = kB[5];
            u64 a0 = 0ull, a1 = 0ull, b0 = 0ull, b1 = 0ull;
            // chain 0: k-pairs 0..5 (floats 0..11); chain 1: k-pairs 6..11 (floats 12..23)
            fma2(a0, qv[0],  a_0.x); fma2(b0, qv[0],  b_0.x);
            fma2(a1, qv[6],  a_3.x); fma2(b1, qv[6],  b_3.x);
            fma2(a0, qv[1],  a_0.y); fma2(b0, qv[1],  b_0.y);
            fma2(a1, qv[7],  a_3.y); fma2(b1, qv[7],  b_3.y);
            fma2(a0, qv[2],  a_1.x); fma2(b0, qv[2],  b_1.x);
            fma2(a1, qv[8],  a_4.x); fma2(b1, qv[8],  b_4.x);
            fma2(a0, qv[3],  a_1.y); fma2(b0, qv[3],  b_1.y);
            fma2(a1, qv[9],  a_4.y); fma2(b1, qv[9],  b_4.y);
            fma2(a0, qv[4],  a_2.x); fma2(b0, qv[4],  b_2.x);
            fma2(a1, qv[10], a_5.x); fma2(b1, qv[10], b_5.x);
            fma2(a0, qv[5],  a_2.y); fma2(b0, qv[5],  b_2.y);
            fma2(a1, qv[11], a_5.y); fma2(b1, qv[11], b_5.y);
            s[j]     = red2(a0) + red2(a1);
            s[j + 1] = red2(b0) + red2(b1);
        }

        // max: 4-way tree partials
        float m0 = s[0], m1 = s[1], m2 = s[2], m3 = s[3];
        #pragma unroll
        for (int j = 4; j < 64; j += 4) {
            m0 = fmaxf(m0, s[j]);     m1 = fmaxf(m1, s[j + 1]);
            m2 = fmaxf(m2, s[j + 2]); m3 = fmaxf(m3, s[j + 3]);
        }
        float mx = fmaxf(fmaxf(m0, m1), fmaxf(m2, m3));

        // exp + sum: 4 partial sums
        float s0 = 0.f, s1 = 0.f, s2 = 0.f, s3 = 0.f;
        #pragma unroll
        for (int j = 0; j < 64; j += 4) {
            s[j]     = __expf((s[j]     - mx) * SCALE);
            s[j + 1] = __expf((s[j + 1] - mx) * SCALE);
            s[j + 2] = __expf((s[j + 2] - mx) * SCALE);
            s[j + 3] = __expf((s[j + 3] - mx) * SCALE);
            s0 += s[j]; s1 += s[j + 1]; s2 += s[j + 2]; s3 += s[j + 3];
        }
        float inv = __fdividef(1.0f, (s0 + s1) + (s2 + s3));

        u64 o[12];
        #pragma unroll
        for (int t = 0; t < 12; t++) o[t] = 0ull;
        // V rows warp-uniform (broadcast), 16B-aligned -> LDS.128
        #pragma unroll
        for (int j = 0; j < 64; j++) {
            const ulonglong2* vp = reinterpret_cast<const ulonglong2*>(Vs + j * QS + co);
            u64 p2 = pack2(s[j], s[j]);
            #pragma unroll
            for (int t = 0; t < 6; t++) {
                ulonglong2 v = vp[t];
                fma2(o[t * 2],     p2, v.x);
                fma2(o[t * 2 + 1], p2, v.y);
            }
        }
        // packed scale + 64-bit stores (1 FMUL2 + 1 STS.64 per pair)
        u64 inv2 = pack2(inv, inv);
        #pragma unroll
        for (int t = 0; t < 12; t++)
            *reinterpret_cast<u64*>(Xs + r * QS + co + t * 2) = mul2(o[t], inv2);
    }

    cp_wait<0>();          // w_proj landed
    __syncthreads();       // O + w_proj visible

    // ---- proj GEMM: out = O @ w_proj + bias ----
    {
        u64 A0[8], A1[8], A2[8];
        #pragma unroll
        for (int i = 0; i < 8; i++) { A0[i] = 0ull; A1[i] = 0ull; A2[i] = 0ull; }

        #pragma unroll 8
        for (int c = 0; c < 96; c += 2) {
            u64 b0 = pack2(W1[c * 96 + lane],      W1[(c + 1) * 96 + lane]);
            u64 b1 = pack2(W1[c * 96 + lane + 32], W1[(c + 1) * 96 + lane + 32]);
            u64 b2 = pack2(W1[c * 96 + lane + 64], W1[(c + 1) * 96 + lane + 64]);
            #pragma unroll
            for (int i = 0; i < 8; i++) {
                u64 xv = *reinterpret_cast<const u64*>(Xs + (r0 + i) * QS + c); // broadcast
                fma2(A0[i], xv, b0);
                fma2(A1[i], xv, b1);
                fma2(A2[i], xv, b2);
            }
        }

        #pragma unroll
        for (int i = 0; i < 8; i++) {
            int go = goff(r0 + i);
            out[go + lane]      = red2(A0[i]) + bb0;
            out[go + lane + 32] = red2(A1[i]) + bb1;
            out[go + lane + 64] = red2(A2[i]) + bb2;
        }
    }
}

extern "C" void kernel_launch(void* const* d_in, const int* in_sizes, int n_in,
                              void* d_out, int out_size)
{
    const float* x      = (const float*)d_in[0];
    const float* w_qkv  = (const float*)d_in[1];
    const float* w_proj = (const float*)d_in[2];
    const float* b_proj = (const float*)d_in[3];
    float* out = (float*)d_out;

    cudaFuncSetAttribute(win3dattn_kernel,
                         cudaFuncAttributeMaxDynamicSharedMemorySize, SMEM_BYTES);
    win3dattn_kernel<<<NWIN, 256, SMEM_BYTES>>>(x, w_qkv, w_proj, b_proj, out);
}